// round 9
// baseline (speedup 1.0000x reference)
#include <cuda_runtime.h>

// Shapes fixed by dataset: x:(T,N,C,2) = (64,16,128,2),
// log_delay:(256,1), log_weight: scalar, noise:(N,C,D,2) = (16,128,256,2)
// out:(T,N,C,D) = (64,16,128,256) fp32.
//
// Store-bound problem. New lever this round: discard.global.L2 on each
// block's output region before writing it. In the steady-state replay loop,
// the previous replay's 128MB of dirty output lines sit in L2; discarding
// them drops the dead writeback (they are fully overwritten this launch).
#define T_DIM 64
#define N_DIM 16
#define C_DIM 128
#define D_DIM 256

// One 64-thread block per (n,c) pair -> 2048 blocks. Each thread owns 4
// consecutive d values -> float4 stores, 512B contiguous per warp per t.
__global__ __launch_bounds__(64) void jeffress_kernel(
    const float* __restrict__ x,
    const float* __restrict__ log_delay,
    const float* __restrict__ log_weight,
    const float* __restrict__ noise,
    float* __restrict__ out)
{
    // x duplicated twice along t so (t - rd) mod 64 becomes base+t.
    __shared__ float xs[2][128];
    __shared__ int maxd_sh[2];

    const int tid = threadIdx.x;       // 0..63
    const int nc  = blockIdx.x;        // 0..2047
    const int n   = nc >> 7;           // C = 128
    const int c   = nc & 127;

    // ---- discard this block's output region from L2 (dead data from the
    // previous replay; every byte is rewritten below). Thread tid owns the
    // t = tid row of this nc: 1KB = 8 x 128B lines. Must complete before any
    // store to the region -> __syncthreads below (also covers smem fill).
    {
        const float* row = out + ((size_t)tid * (N_DIM * C_DIM) + nc) * D_DIM;
        #pragma unroll
        for (int l = 0; l < 8; l++) {
            asm volatile("discard.global.L2 [%0], 128;"
                         :: "l"(row + l * 32) : "memory");
        }
    }

    const float w = expf(__ldg(log_weight));   // > 0

    // ---- load x[t=tid] (both j), pre-scaled by w, duplicated for wrap
    {
        const float2 v2 = *reinterpret_cast<const float2*>(
            x + (((size_t)tid * N_DIM + n) * C_DIM + c) * 2);
        float v0 = w * v2.x;
        float v1 = w * v2.y;
        xs[0][tid]      = v0;
        xs[0][tid + 64] = v0;
        xs[1][tid]      = v1;
        xs[1][tid + 64] = v1;
    }
    __syncthreads();   // orders discards before all stores; publishes xs

    // ---- argmax over t per stream j: warp j reduces stream j.
    // First-occurrence semantics (jnp.argmax): strictly-greater wins.
    {
        const int wj   = tid >> 5;     // stream index
        const int lane = tid & 31;
        float v1 = xs[wj][lane];
        float v2 = xs[wj][lane + 32];
        float v; int idx;
        if (v2 > v1) { v = v2; idx = lane + 32; } else { v = v1; idx = lane; }
        #pragma unroll
        for (int o = 16; o > 0; o >>= 1) {
            float ov = __shfl_xor_sync(0xffffffffu, v, o);
            int   oi = __shfl_xor_sync(0xffffffffu, idx, o);
            if (ov > v || (ov == v && oi < idx)) { v = ov; idx = oi; }
        }
        if (lane == 0) maxd_sh[wj] = (T_DIM - 1) - idx;
    }
    __syncthreads();

    const int d0  = tid << 2;          // 4 consecutive d per thread
    const int md0 = maxd_sh[0];
    const int md1 = maxd_sh[1];

    // noise[(nc*256 + d)*2 + j]: 8 consecutive floats -> two float4 loads
    const float4* nzp = reinterpret_cast<const float4*>(
        noise + ((size_t)nc * D_DIM + d0) * 2);
    float4 nzA = __ldg(nzp);
    float4 nzB = __ldg(nzp + 1);
    float nz0[4] = {nzA.x, nzA.z, nzB.x, nzB.z};   // j = 0
    float nz1[4] = {nzA.y, nzA.w, nzB.y, nzB.w};   // j = 1

    // ---- per-stream delays -> base pointers into the duplicated array
    const float* b0[4];
    const float* b1[4];
    #pragma unroll
    for (int i = 0; i < 4; i++) {
        int d = d0 + i;
        float s0 = 64.0f * expf(__ldg(log_delay + d));
        float s1 = 64.0f * expf(__ldg(log_delay + (D_DIM - 1 - d)));  // flip
        float f0 = floorf(s0), f1 = floorf(s1);
        int r0 = (int)f0 + ((nz0[i] < (s0 - f0)) ? 1 : 0);
        int r1 = (int)f1 + ((nz1[i] < (s1 - f1)) ? 1 : 0);
        int rd0 = min(r0, md0);
        int rd1 = min(r1, md1);
        b0[i] = &xs[0][64 - rd0];      // b[t] == x[(t - rd) mod 64]
        b1[i] = &xs[1][64 - rd1];
    }

    // ---- main scan: y_t = 0.5*y_{t-1} + x_shifted, out = y(j=0)+y(j=1)
    float y0[4] = {0.f, 0.f, 0.f, 0.f};
    float y1[4] = {0.f, 0.f, 0.f, 0.f};
    float4* outp = reinterpret_cast<float4*>(out + (size_t)nc * D_DIM + d0);
    const size_t tstride4 = (size_t)N_DIM * C_DIM * D_DIM / 4;

    #pragma unroll 8
    for (int t = 0; t < T_DIM; t++) {
        float4 v;
        #pragma unroll
        for (int i = 0; i < 4; i++) {
            y0[i] = y0[i] * 0.5f + b0[i][t];
            y1[i] = y1[i] * 0.5f + b1[i][t];
        }
        v.x = y0[0] + y1[0];
        v.y = y0[1] + y1[1];
        v.z = y0[2] + y1[2];
        v.w = y0[3] + y1[3];
        *outp = v;
        outp += tstride4;
    }
}

extern "C" void kernel_launch(void* const* d_in, const int* in_sizes, int n_in,
                              void* d_out, int out_size) {
    const float* x          = (const float*)d_in[0];
    const float* log_delay  = (const float*)d_in[1];
    const float* log_weight = (const float*)d_in[2];
    const float* noise      = (const float*)d_in[3];
    float* out = (float*)d_out;

    jeffress_kernel<<<N_DIM * C_DIM, 64>>>(x, log_delay, log_weight, noise, out);
}

// round 10
// speedup vs baseline: 1.0940x; 1.0940x over previous
#include <cuda_runtime.h>

// Shapes fixed by dataset: x:(T,N,C,2) = (64,16,128,2),
// log_delay:(256,1), log_weight: scalar, noise:(N,C,D,2) = (16,128,256,2)
// out:(T,N,C,D) = (64,16,128,256) fp32.
//
// FINAL (verified twice at 27.14us, rounds 2 & 8). The problem is
// store-bound at the hardware floor: 128MB fp32 output per launch. Profiled
// kernel sits on the L2 write-sector port (~3150 B/cyc); steady-state bench
// on the HBM write stream. Falsified levers: occupancy (16-54% invariant),
// LDS reduction (8x->2x invariant), store width/policy (.wb/.wt/.cs), TMA
// bulk stores (regressed), L2 discard (regressed hard).
#define T_DIM 64
#define N_DIM 16
#define C_DIM 128
#define D_DIM 256

// One 64-thread block per (n,c) pair -> 2048 blocks. Each thread owns 4
// consecutive d values -> float4 stores, 512B contiguous per warp per t.
__global__ __launch_bounds__(64) void jeffress_kernel(
    const float* __restrict__ x,
    const float* __restrict__ log_delay,
    const float* __restrict__ log_weight,
    const float* __restrict__ noise,
    float* __restrict__ out)
{
    // x duplicated twice along t so (t - rd) mod 64 becomes base+t.
    __shared__ float xs[2][128];
    __shared__ int maxd_sh[2];

    const int tid = threadIdx.x;       // 0..63
    const int nc  = blockIdx.x;        // 0..2047
    const int n   = nc >> 7;           // C = 128
    const int c   = nc & 127;
    const float w = expf(__ldg(log_weight));   // > 0

    // ---- load x[t=tid] (both j), pre-scaled by w, duplicated for wrap
    {
        const float2 v2 = *reinterpret_cast<const float2*>(
            x + (((size_t)tid * N_DIM + n) * C_DIM + c) * 2);
        float v0 = w * v2.x;
        float v1 = w * v2.y;
        xs[0][tid]      = v0;
        xs[0][tid + 64] = v0;
        xs[1][tid]      = v1;
        xs[1][tid + 64] = v1;
    }
    __syncthreads();

    // ---- argmax over t per stream j: warp j reduces stream j.
    // First-occurrence semantics (jnp.argmax): strictly-greater wins.
    {
        const int wj   = tid >> 5;     // stream index
        const int lane = tid & 31;
        float v1 = xs[wj][lane];
        float v2 = xs[wj][lane + 32];
        float v; int idx;
        if (v2 > v1) { v = v2; idx = lane + 32; } else { v = v1; idx = lane; }
        #pragma unroll
        for (int o = 16; o > 0; o >>= 1) {
            float ov = __shfl_xor_sync(0xffffffffu, v, o);
            int   oi = __shfl_xor_sync(0xffffffffu, idx, o);
            if (ov > v || (ov == v && oi < idx)) { v = ov; idx = oi; }
        }
        if (lane == 0) maxd_sh[wj] = (T_DIM - 1) - idx;
    }
    __syncthreads();

    const int d0  = tid << 2;          // 4 consecutive d per thread
    const int md0 = maxd_sh[0];
    const int md1 = maxd_sh[1];

    // noise[(nc*256 + d)*2 + j]: 8 consecutive floats -> two float4 loads
    const float4* nzp = reinterpret_cast<const float4*>(
        noise + ((size_t)nc * D_DIM + d0) * 2);
    float4 nzA = __ldg(nzp);
    float4 nzB = __ldg(nzp + 1);
    float nz0[4] = {nzA.x, nzA.z, nzB.x, nzB.z};   // j = 0
    float nz1[4] = {nzA.y, nzA.w, nzB.y, nzB.w};   // j = 1

    // ---- per-stream delays -> base pointers into the duplicated array
    const float* b0[4];
    const float* b1[4];
    #pragma unroll
    for (int i = 0; i < 4; i++) {
        int d = d0 + i;
        float s0 = 64.0f * expf(__ldg(log_delay + d));
        float s1 = 64.0f * expf(__ldg(log_delay + (D_DIM - 1 - d)));  // flip
        float f0 = floorf(s0), f1 = floorf(s1);
        int r0 = (int)f0 + ((nz0[i] < (s0 - f0)) ? 1 : 0);
        int r1 = (int)f1 + ((nz1[i] < (s1 - f1)) ? 1 : 0);
        int rd0 = min(r0, md0);
        int rd1 = min(r1, md1);
        b0[i] = &xs[0][64 - rd0];      // b[t] == x[(t - rd) mod 64]
        b1[i] = &xs[1][64 - rd1];
    }

    // ---- main scan: y_t = 0.5*y_{t-1} + x_shifted, out = y(j=0)+y(j=1)
    float y0[4] = {0.f, 0.f, 0.f, 0.f};
    float y1[4] = {0.f, 0.f, 0.f, 0.f};
    float4* outp = reinterpret_cast<float4*>(out + (size_t)nc * D_DIM + d0);
    const size_t tstride4 = (size_t)N_DIM * C_DIM * D_DIM / 4;

    #pragma unroll 8
    for (int t = 0; t < T_DIM; t++) {
        float4 v;
        #pragma unroll
        for (int i = 0; i < 4; i++) {
            y0[i] = y0[i] * 0.5f + b0[i][t];
            y1[i] = y1[i] * 0.5f + b1[i][t];
        }
        v.x = y0[0] + y1[0];
        v.y = y0[1] + y1[1];
        v.z = y0[2] + y1[2];
        v.w = y0[3] + y1[3];
        *outp = v;
        outp += tstride4;
    }
}

extern "C" void kernel_launch(void* const* d_in, const int* in_sizes, int n_in,
                              void* d_out, int out_size) {
    const float* x          = (const float*)d_in[0];
    const float* log_delay  = (const float*)d_in[1];
    const float* log_weight = (const float*)d_in[2];
    const float* noise      = (const float*)d_in[3];
    float* out = (float*)d_out;

    jeffress_kernel<<<N_DIM * C_DIM, 64>>>(x, log_delay, log_weight, noise, out);
}

// round 11
// speedup vs baseline: 1.1133x; 1.0177x over previous
#include <cuda_runtime.h>

// Shapes fixed by dataset: x:(T,N,C,2) = (64,16,128,2),
// log_delay:(256,1), log_weight: scalar, noise:(N,C,D,2) = (16,128,256,2)
// out:(T,N,C,D) = (64,16,128,256) fp32.
//
// FINAL — store-bound at the hardware floor (best measured 27.14us, verified
// rounds 2 & 8; run-to-run noise +-0.4us). 134MB/launch mandatory memory
// stream: profiled kernel pinned at the L2 write-sector port (~3150 B/cyc,
// ~half the LTS load cap), steady-state bench additionally bound by HBM
// writeback of the prior replay's dirty output. Falsified levers: occupancy
// 16-54%, LDS 8x->2x, store width/policy (.wb/.wt/.cs), TMA bulk stores,
// L2 discard — all invariant or regressions.
#define T_DIM 64
#define N_DIM 16
#define C_DIM 128
#define D_DIM 256

// One 64-thread block per (n,c) pair -> 2048 blocks. Each thread owns 4
// consecutive d values -> float4 stores, 512B contiguous per warp per t.
__global__ __launch_bounds__(64) void jeffress_kernel(
    const float* __restrict__ x,
    const float* __restrict__ log_delay,
    const float* __restrict__ log_weight,
    const float* __restrict__ noise,
    float* __restrict__ out)
{
    // x duplicated twice along t so (t - rd) mod 64 becomes base+t.
    __shared__ float xs[2][128];
    __shared__ int maxd_sh[2];

    const int tid = threadIdx.x;       // 0..63
    const int nc  = blockIdx.x;        // 0..2047
    const int n   = nc >> 7;           // C = 128
    const int c   = nc & 127;
    const float w = expf(__ldg(log_weight));   // > 0

    // ---- load x[t=tid] (both j), pre-scaled by w, duplicated for wrap
    {
        const float2 v2 = *reinterpret_cast<const float2*>(
            x + (((size_t)tid * N_DIM + n) * C_DIM + c) * 2);
        float v0 = w * v2.x;
        float v1 = w * v2.y;
        xs[0][tid]      = v0;
        xs[0][tid + 64] = v0;
        xs[1][tid]      = v1;
        xs[1][tid + 64] = v1;
    }
    __syncthreads();

    // ---- argmax over t per stream j: warp j reduces stream j.
    // First-occurrence semantics (jnp.argmax): strictly-greater wins.
    {
        const int wj   = tid >> 5;     // stream index
        const int lane = tid & 31;
        float v1 = xs[wj][lane];
        float v2 = xs[wj][lane + 32];
        float v; int idx;
        if (v2 > v1) { v = v2; idx = lane + 32; } else { v = v1; idx = lane; }
        #pragma unroll
        for (int o = 16; o > 0; o >>= 1) {
            float ov = __shfl_xor_sync(0xffffffffu, v, o);
            int   oi = __shfl_xor_sync(0xffffffffu, idx, o);
            if (ov > v || (ov == v && oi < idx)) { v = ov; idx = oi; }
        }
        if (lane == 0) maxd_sh[wj] = (T_DIM - 1) - idx;
    }
    __syncthreads();

    const int d0  = tid << 2;          // 4 consecutive d per thread
    const int md0 = maxd_sh[0];
    const int md1 = maxd_sh[1];

    // noise[(nc*256 + d)*2 + j]: 8 consecutive floats -> two float4 loads
    const float4* nzp = reinterpret_cast<const float4*>(
        noise + ((size_t)nc * D_DIM + d0) * 2);
    float4 nzA = __ldg(nzp);
    float4 nzB = __ldg(nzp + 1);
    float nz0[4] = {nzA.x, nzA.z, nzB.x, nzB.z};   // j = 0
    float nz1[4] = {nzA.y, nzA.w, nzB.y, nzB.w};   // j = 1

    // ---- per-stream delays -> base pointers into the duplicated array
    const float* b0[4];
    const float* b1[4];
    #pragma unroll
    for (int i = 0; i < 4; i++) {
        int d = d0 + i;
        float s0 = 64.0f * expf(__ldg(log_delay + d));
        float s1 = 64.0f * expf(__ldg(log_delay + (D_DIM - 1 - d)));  // flip
        float f0 = floorf(s0), f1 = floorf(s1);
        int r0 = (int)f0 + ((nz0[i] < (s0 - f0)) ? 1 : 0);
        int r1 = (int)f1 + ((nz1[i] < (s1 - f1)) ? 1 : 0);
        int rd0 = min(r0, md0);
        int rd1 = min(r1, md1);
        b0[i] = &xs[0][64 - rd0];      // b[t] == x[(t - rd) mod 64]
        b1[i] = &xs[1][64 - rd1];
    }

    // ---- main scan: y_t = 0.5*y_{t-1} + x_shifted, out = y(j=0)+y(j=1)
    float y0[4] = {0.f, 0.f, 0.f, 0.f};
    float y1[4] = {0.f, 0.f, 0.f, 0.f};
    float4* outp = reinterpret_cast<float4*>(out + (size_t)nc * D_DIM + d0);
    const size_t tstride4 = (size_t)N_DIM * C_DIM * D_DIM / 4;

    #pragma unroll 8
    for (int t = 0; t < T_DIM; t++) {
        float4 v;
        #pragma unroll
        for (int i = 0; i < 4; i++) {
            y0[i] = y0[i] * 0.5f + b0[i][t];
            y1[i] = y1[i] * 0.5f + b1[i][t];
        }
        v.x = y0[0] + y1[0];
        v.y = y0[1] + y1[1];
        v.z = y0[2] + y1[2];
        v.w = y0[3] + y1[3];
        *outp = v;
        outp += tstride4;
    }
}

extern "C" void kernel_launch(void* const* d_in, const int* in_sizes, int n_in,
                              void* d_out, int out_size) {
    const float* x          = (const float*)d_in[0];
    const float* log_delay  = (const float*)d_in[1];
    const float* log_weight = (const float*)d_in[2];
    const float* noise      = (const float*)d_in[3];
    float* out = (float*)d_out;

    jeffress_kernel<<<N_DIM * C_DIM, 64>>>(x, log_delay, log_weight, noise, out);
}